// round 1
// baseline (speedup 1.0000x reference)
#include <cuda_runtime.h>

typedef unsigned long long ull;

#define TPB   128
#define PAIRS 2

// G_w[m][n] constants, value duplicated into both 32-bit halves for f32x2.
__device__ ull gGd[4 * 81];

// ---------- f32x2 helpers (Blackwell packed fp32) ----------
__device__ __forceinline__ ull ffma2(ull a, ull b, ull c) {
    ull d;
    asm("fma.rn.f32x2 %0, %1, %2, %3;" : "=l"(d) : "l"(a), "l"(b), "l"(c));
    return d;
}
__device__ __forceinline__ ull pk(float lo, float hi) {
    ull r;
    unsigned int l = __float_as_uint(lo), h = __float_as_uint(hi);
    asm("mov.b64 %0, {%1, %2};" : "=l"(r) : "r"(l), "r"(h));
    return r;
}
__device__ __forceinline__ void upk(ull v, float &lo, float &hi) {
    unsigned int l, h;
    asm("mov.b64 {%0, %1}, %2;" : "=r"(l), "=r"(h) : "l"(v));
    lo = __uint_as_float(l);
    hi = __uint_as_float(h);
}

// ============================================================
// Setup kernel (1 block, 128 threads):
// Build 16x16 circuit unitary M from q_weights, then for each wire w:
//   A_w[i][j] = sum_k sign_w(k) * Re(conj(M[k,j]) M[k,i])   (real, symmetric)
// then transform each qubit index-pair (i_w,j_w) into the (1, cos, sin)
// basis, producing G_w (9x9) with m = a0*3+a1 (qubits 0,1), n = a2*3+a3.
// ============================================================
__global__ void setup_kernel(const float* __restrict__ qw, int nlayers) {
    __shared__ float Mr[16][16];
    __shared__ float Mi[16][16];
    __shared__ float bufA[256];
    __shared__ float bufB[192];

    const int tid = threadIdx.x;

    // M = I
    for (int i = tid; i < 256; i += TPB) {
        Mr[i / 16][i % 16] = (i / 16 == i % 16) ? 1.0f : 0.0f;
        Mi[i / 16][i % 16] = 0.0f;
    }
    __syncthreads();

    for (int l = 0; l < nlayers; l++) {
        // Rot gates on wires 0..3
        for (int w = 0; w < 4; w++) {
            float phi = qw[(l * 4 + w) * 3 + 0];
            float th  = qw[(l * 4 + w) * 3 + 1];
            float om  = qw[(l * 4 + w) * 3 + 2];
            float c, s, ca, sa, cb, sb;
            sincosf(0.5f * th, &s, &c);
            sincosf(0.5f * (phi + om), &sa, &ca);   // em = (ca, -sa)
            sincosf(0.5f * (phi - om), &sb, &cb);   // ed = (cb,  sb)
            float g00r =  ca * c, g00i = -sa * c;
            float g01r = -cb * s, g01i = -sb * s;
            float g10r =  cb * s, g10i = -sb * s;
            float g11r =  ca * c, g11i =  sa * c;

            int mask = 8 >> w;
            // 8 row-pairs x 16 cols = 128 tasks
            int pr = tid / 16, col = tid % 16;
            int hi = (pr & ~(mask - 1)) << 1;
            int lo = pr & (mask - 1);
            int r0 = hi | lo;
            int r1 = r0 | mask;
            float ar = Mr[r0][col], ai = Mi[r0][col];
            float br = Mr[r1][col], bi = Mi[r1][col];
            float n0r = g00r * ar - g00i * ai + g01r * br - g01i * bi;
            float n0i = g00r * ai + g00i * ar + g01r * bi + g01i * br;
            float n1r = g10r * ar - g10i * ai + g11r * br - g11i * bi;
            float n1i = g10r * ai + g10i * ar + g11r * bi + g11i * br;
            Mr[r0][col] = n0r; Mi[r0][col] = n0i;
            Mr[r1][col] = n1r; Mi[r1][col] = n1i;
            __syncthreads();
        }
        // CNOT ring: control w, target (w+1)%4
        for (int w = 0; w < 4; w++) {
            int cm = 8 >> w;
            int tm = 8 >> ((w + 1) & 3);
            if (tid < 64) {
                int rr = tid / 16, col = tid % 16;
                int fm = 15 & ~cm & ~tm;   // two free bit positions
                int r = cm, k = 0;
                for (int b = 0; b < 4; b++) {
                    int m = 1 << b;
                    if (fm & m) { if ((rr >> k) & 1) r |= m; k++; }
                }
                int r2 = r | tm;
                float t;
                t = Mr[r][col]; Mr[r][col] = Mr[r2][col]; Mr[r2][col] = t;
                t = Mi[r][col]; Mi[r][col] = Mi[r2][col]; Mi[r2][col] = t;
            }
            __syncthreads();
        }
    }

    // Per-wire quadratic-form tensor -> G_w
    for (int w = 0; w < 4; w++) {
        int mw = 8 >> w;
        // A_w, stored directly in "pair index" layout b0 = sum (i_q*2+j_q)*4^(3-q)
        for (int e = tid; e < 256; e += TPB) {
            int i = e / 16, j = e % 16;
            float sum = 0.0f;
            for (int k = 0; k < 16; k++) {
                float sgn = (k & mw) ? -1.0f : 1.0f;
                sum += sgn * (Mr[k][i] * Mr[k][j] + Mi[k][i] * Mi[k][j]);
            }
            int b0 = 0;
            for (int q = 0; q < 4; q++) {
                int iw = (i >> (3 - q)) & 1;
                int jw = (j >> (3 - q)) & 1;
                b0 = b0 * 4 + (iw * 2 + jw);
            }
            bufA[b0] = sum;
        }
        __syncthreads();

        // 4 contraction stages: pair-index (4) -> (1,C,S) basis (3)
        float* bin  = bufA;
        float* bout = bufB;
        int pre = 1, post = 64;
        for (int q = 0; q < 4; q++) {
            int nout = pre * 3 * post;
            for (int e = tid; e < nout; e += TPB) {
                int po = e % post;
                int al = (e / post) % 3;
                int pr2 = e / (post * 3);
                const float* ip = bin + pr2 * 4 * post;
                float v;
                if (al == 0)      v = 0.5f * (ip[0 * post + po] + ip[3 * post + po]);
                else if (al == 1) v = 0.5f * (ip[0 * post + po] - ip[3 * post + po]);
                else              v = 0.5f * (ip[1 * post + po] + ip[2 * post + po]);
                bout[pr2 * 3 * post + al * post + po] = v;
            }
            __syncthreads();
            float* t = bin; bin = bout; bout = t;
            pre *= 3; post /= 4;
        }
        // bin now holds 81 values T[m*9+n]; duplicate into both f32 halves
        for (int e = tid; e < 81; e += TPB) {
            unsigned int bits = __float_as_uint(bin[e]);
            gGd[w * 81 + e] = ((ull)bits << 32) | (ull)bits;
        }
        __syncthreads();
    }
}

// ============================================================
// Main kernel: each thread processes PAIRS f32x2-packed sample pairs.
// out[b][w] = sum_{m,n} G_w[m][n] * Q[m] * P[n],
//   Q = (1,C0,S0) x (1,C1,S1),  P = (1,C2,S2) x (1,C3,S3)
// ============================================================
__global__ void __launch_bounds__(TPB) qmain_kernel(
    const float4* __restrict__ xin, float4* __restrict__ xout, int halfB) {
    __shared__ __align__(16) ull sG[4][9][10];   // padded rows (80B) for LDS.128
    for (int i = threadIdx.x; i < 324; i += TPB)
        sG[i / 81][(i / 9) % 9][i % 9] = gGd[i];
    __syncthreads();

    int base = blockIdx.x * (TPB * PAIRS) + threadIdx.x;

    ull P[PAIRS][8], Q[PAIRS][8];
    int idxs[PAIRS];

#pragma unroll
    for (int p = 0; p < PAIRS; p++) {
        int idx = base + p * TPB;
        if (idx >= halfB) idx = halfB - 1;   // duplicate-safe clamp
        idxs[p] = idx;
        float4 xa = xin[idx];
        float4 xb = xin[idx + halfB];
        float c0a, s0a, c1a, s1a, c2a, s2a, c3a, s3a;
        float c0b, s0b, c1b, s1b, c2b, s2b, c3b, s3b;
        __sincosf(xa.x, &s0a, &c0a);
        __sincosf(xa.y, &s1a, &c1a);
        __sincosf(xa.z, &s2a, &c2a);
        __sincosf(xa.w, &s3a, &c3a);
        __sincosf(xb.x, &s0b, &c0b);
        __sincosf(xb.y, &s1b, &c1b);
        __sincosf(xb.z, &s2b, &c2b);
        __sincosf(xb.w, &s3b, &c3b);
        // Q (qubits 0,1), entries m = 1..8
        Q[p][0] = pk(c1a,         c1b);
        Q[p][1] = pk(s1a,         s1b);
        Q[p][2] = pk(c0a,         c0b);
        Q[p][3] = pk(c0a * c1a,   c0b * c1b);
        Q[p][4] = pk(c0a * s1a,   c0b * s1b);
        Q[p][5] = pk(s0a,         s0b);
        Q[p][6] = pk(s0a * c1a,   s0b * c1b);
        Q[p][7] = pk(s0a * s1a,   s0b * s1b);
        // P (qubits 2,3), entries n = 1..8
        P[p][0] = pk(c3a,         c3b);
        P[p][1] = pk(s3a,         s3b);
        P[p][2] = pk(c2a,         c2b);
        P[p][3] = pk(c2a * c3a,   c2b * c3b);
        P[p][4] = pk(c2a * s3a,   c2b * s3b);
        P[p][5] = pk(s2a,         s2b);
        P[p][6] = pk(s2a * c3a,   s2b * c3b);
        P[p][7] = pk(s2a * s3a,   s2b * s3b);
    }

    float resA[PAIRS][4], resB[PAIRS][4];
#pragma unroll
    for (int w = 0; w < 4; w++) {
        ull acc[PAIRS];
#pragma unroll
        for (int m = 0; m < 9; m++) {
            const ulonglong2* g2 = reinterpret_cast<const ulonglong2*>(&sG[w][m][0]);
            ulonglong2 gab = g2[0];
            ulonglong2 gcd2 = g2[1];
            ulonglong2 gef = g2[2];
            ulonglong2 ggh = g2[3];
            ull g8 = sG[w][m][8];
#pragma unroll
            for (int p = 0; p < PAIRS; p++) {
                ull t = gab.x;
                t = ffma2(gab.y,  P[p][0], t);
                t = ffma2(gcd2.x, P[p][1], t);
                t = ffma2(gcd2.y, P[p][2], t);
                t = ffma2(gef.x,  P[p][3], t);
                t = ffma2(gef.y,  P[p][4], t);
                t = ffma2(ggh.x,  P[p][5], t);
                t = ffma2(ggh.y,  P[p][6], t);
                t = ffma2(g8,     P[p][7], t);
                if (m == 0) acc[p] = t;                       // Q[0] = 1
                else        acc[p] = ffma2(Q[p][m - 1], t, acc[p]);
            }
        }
#pragma unroll
        for (int p = 0; p < PAIRS; p++) upk(acc[p], resA[p][w], resB[p][w]);
    }

#pragma unroll
    for (int p = 0; p < PAIRS; p++) {
        xout[idxs[p]]         = make_float4(resA[p][0], resA[p][1], resA[p][2], resA[p][3]);
        xout[idxs[p] + halfB] = make_float4(resB[p][0], resB[p][1], resB[p][2], resB[p][3]);
    }
}

extern "C" void kernel_launch(void* const* d_in, const int* in_sizes, int n_in,
                              void* d_out, int out_size) {
    // Identify tensors by size: q_weights is tiny (nlayers*4*3), inputs is B*4.
    int xi = 0, wi = 1;
    if (n_in >= 2 && in_sizes[0] < in_sizes[1]) { xi = 1; wi = 0; }
    const float* x  = (const float*)d_in[xi];
    const float* qw = (const float*)d_in[wi];
    int B = in_sizes[xi] / 4;
    int nlayers = in_sizes[wi] / 12;
    int halfB = B / 2;

    setup_kernel<<<1, TPB>>>(qw, nlayers);

    int blocks = (halfB + TPB * PAIRS - 1) / (TPB * PAIRS);
    qmain_kernel<<<blocks, TPB>>>((const float4*)x, (float4*)d_out, halfB);
}

// round 2
// speedup vs baseline: 1.0696x; 1.0696x over previous
#include <cuda_runtime.h>

typedef unsigned long long ull;

#define TPB 128

// G_w[m][n] constants, value duplicated into both 32-bit halves for f32x2.
__device__ ull gGd[4 * 81];

// ---------- f32x2 helpers (Blackwell packed fp32) ----------
__device__ __forceinline__ ull ffma2(ull a, ull b, ull c) {
    ull d;
    asm("fma.rn.f32x2 %0, %1, %2, %3;" : "=l"(d) : "l"(a), "l"(b), "l"(c));
    return d;
}
__device__ __forceinline__ ull pk(float lo, float hi) {
    ull r;
    unsigned int l = __float_as_uint(lo), h = __float_as_uint(hi);
    asm("mov.b64 %0, {%1, %2};" : "=l"(r) : "r"(l), "r"(h));
    return r;
}
__device__ __forceinline__ void upk(ull v, float &lo, float &hi) {
    unsigned int l, h;
    asm("mov.b64 {%0, %1}, %2;" : "=r"(l), "=r"(h) : "l"(v));
    lo = __uint_as_float(l);
    hi = __uint_as_float(h);
}

// ============================================================
// Setup kernel (1 block, 128 threads):
// Phase 1 (whole block): build 16x16 circuit unitary M from q_weights.
// Phase 2 (one warp per wire w, no block barriers):
//   A_w[i][j] = sum_k sign_w(k) * Re(conj(M[k,j]) M[k,i])
//   then transform each qubit index-pair into the (1,C,S) basis -> G_w (9x9).
// ============================================================
__global__ void setup_kernel(const float* __restrict__ qw, int nlayers) {
    __shared__ float Mr[16][16];
    __shared__ float Mi[16][16];
    __shared__ float bufA[4][256];
    __shared__ float bufB[4][192];

    const int tid = threadIdx.x;
    const int wid = tid >> 5;
    const int lane = tid & 31;

    // M = I
    for (int i = tid; i < 256; i += TPB) {
        Mr[i / 16][i % 16] = (i / 16 == i % 16) ? 1.0f : 0.0f;
        Mi[i / 16][i % 16] = 0.0f;
    }
    __syncthreads();

    for (int l = 0; l < nlayers; l++) {
        // Rot gates on wires 0..3
        for (int w = 0; w < 4; w++) {
            float phi = qw[(l * 4 + w) * 3 + 0];
            float th  = qw[(l * 4 + w) * 3 + 1];
            float om  = qw[(l * 4 + w) * 3 + 2];
            float c, s, ca, sa, cb, sb;
            sincosf(0.5f * th, &s, &c);
            sincosf(0.5f * (phi + om), &sa, &ca);   // em = (ca, -sa)
            sincosf(0.5f * (phi - om), &sb, &cb);   // ed = (cb,  sb)
            float g00r =  ca * c, g00i = -sa * c;
            float g01r = -cb * s, g01i = -sb * s;
            float g10r =  cb * s, g10i = -sb * s;
            float g11r =  ca * c, g11i =  sa * c;

            int mask = 8 >> w;
            int pr = tid / 16, col = tid % 16;
            int hi = (pr & ~(mask - 1)) << 1;
            int lo = pr & (mask - 1);
            int r0 = hi | lo;
            int r1 = r0 | mask;
            float ar = Mr[r0][col], ai = Mi[r0][col];
            float br = Mr[r1][col], bi = Mi[r1][col];
            float n0r = g00r * ar - g00i * ai + g01r * br - g01i * bi;
            float n0i = g00r * ai + g00i * ar + g01r * bi + g01i * br;
            float n1r = g10r * ar - g10i * ai + g11r * br - g11i * bi;
            float n1i = g10r * ai + g10i * ar + g11r * bi + g11i * br;
            Mr[r0][col] = n0r; Mi[r0][col] = n0i;
            Mr[r1][col] = n1r; Mi[r1][col] = n1i;
            __syncthreads();
        }
        // CNOT ring: control w, target (w+1)%4
        for (int w = 0; w < 4; w++) {
            int cm = 8 >> w;
            int tm = 8 >> ((w + 1) & 3);
            if (tid < 64) {
                int rr = tid / 16, col = tid % 16;
                int fm = 15 & ~cm & ~tm;
                int r = cm, k = 0;
                for (int b = 0; b < 4; b++) {
                    int m = 1 << b;
                    if (fm & m) { if ((rr >> k) & 1) r |= m; k++; }
                }
                int r2 = r | tm;
                float t;
                t = Mr[r][col]; Mr[r][col] = Mr[r2][col]; Mr[r2][col] = t;
                t = Mi[r][col]; Mi[r][col] = Mi[r2][col]; Mi[r2][col] = t;
            }
            __syncthreads();
        }
    }

    // ---- Phase 2: each warp handles one wire, warp-local sync only ----
    {
        const int w = wid;          // wire index = warp id (0..3)
        const int mw = 8 >> w;
        float* bA = bufA[w];
        float* bB = bufB[w];

        // A_w, stored in "pair index" layout b0 = sum (i_q*2+j_q)*4^(3-q)
        for (int e = lane; e < 256; e += 32) {
            int i = e / 16, j = e % 16;
            float sum = 0.0f;
            for (int k = 0; k < 16; k++) {
                float sgn = (k & mw) ? -1.0f : 1.0f;
                sum += sgn * (Mr[k][i] * Mr[k][j] + Mi[k][i] * Mi[k][j]);
            }
            int b0 = 0;
            for (int q = 0; q < 4; q++) {
                int iw = (i >> (3 - q)) & 1;
                int jw = (j >> (3 - q)) & 1;
                b0 = b0 * 4 + (iw * 2 + jw);
            }
            bA[b0] = sum;
        }
        __syncwarp();

        // 4 contraction stages: pair-index (4) -> (1,C,S) basis (3)
        float* bin  = bA;
        float* bout = bB;
        int pre = 1, post = 64;
        for (int q = 0; q < 4; q++) {
            int nout = pre * 3 * post;
            for (int e = lane; e < nout; e += 32) {
                int po = e % post;
                int al = (e / post) % 3;
                int pr2 = e / (post * 3);
                const float* ip = bin + pr2 * 4 * post;
                float v;
                if (al == 0)      v = 0.5f * (ip[0 * post + po] + ip[3 * post + po]);
                else if (al == 1) v = 0.5f * (ip[0 * post + po] - ip[3 * post + po]);
                else              v = 0.5f * (ip[1 * post + po] + ip[2 * post + po]);
                bout[pr2 * 3 * post + al * post + po] = v;
            }
            __syncwarp();
            float* t = bin; bin = bout; bout = t;
            pre *= 3; post /= 4;
        }
        // bin holds 81 values T[m*9+n]; duplicate into both f32 halves
        for (int e = lane; e < 81; e += 32) {
            unsigned int bits = __float_as_uint(bin[e]);
            gGd[w * 81 + e] = ((ull)bits << 32) | (ull)bits;
        }
    }
}

// ============================================================
// Main kernel: each thread processes 2 f32x2-packed sample pairs (4 samples).
// out[b][w] = sum_{m,n} G_w[m][n] * Q_m * P_n with
//   Q = (1,C0,S0)x(1,C1,S1), P = (1,C2,S2)x(1,C3,S3)
// P and Q are contracted on the fly (never materialized):
//   row r_m = sum_c u2_c * (g[3c] + C3 g[3c+1] + S3 g[3c+2])
//   acc_a accumulates r_{3a+b} weighted by (1,C1,S1); out = u0 . acc
// Three independent 2-deep ffma2 sub-chains per row x 2 pairs = high ILP.
// ============================================================
__global__ void __launch_bounds__(TPB, 5) qmain_kernel(
    const float4* __restrict__ xin, float4* __restrict__ xout, int halfB) {
    __shared__ __align__(16) ull sG[4][9][10];   // padded rows (80B) for LDS.128
    for (int i = threadIdx.x; i < 324; i += TPB)
        sG[i / 81][(i / 9) % 9][i % 9] = gGd[i];
    __syncthreads();

    int base = blockIdx.x * (TPB * 2) + threadIdx.x;

    // per-pair trig, f32x2-packed: [p][qubit] with C and S
    ull C0[2], S0[2], C1[2], S1[2], C2[2], S2[2], C3[2], S3[2];
    int idxs[2];

#pragma unroll
    for (int p = 0; p < 2; p++) {
        int idx = base + p * TPB;
        if (idx >= halfB) idx = halfB - 1;   // duplicate-safe clamp
        idxs[p] = idx;
        float4 xa = xin[idx];
        float4 xb = xin[idx + halfB];
        float c0a, s0a, c1a, s1a, c2a, s2a, c3a, s3a;
        float c0b, s0b, c1b, s1b, c2b, s2b, c3b, s3b;
        __sincosf(xa.x, &s0a, &c0a);
        __sincosf(xa.y, &s1a, &c1a);
        __sincosf(xa.z, &s2a, &c2a);
        __sincosf(xa.w, &s3a, &c3a);
        __sincosf(xb.x, &s0b, &c0b);
        __sincosf(xb.y, &s1b, &c1b);
        __sincosf(xb.z, &s2b, &c2b);
        __sincosf(xb.w, &s3b, &c3b);
        C0[p] = pk(c0a, c0b);  S0[p] = pk(s0a, s0b);
        C1[p] = pk(c1a, c1b);  S1[p] = pk(s1a, s1b);
        C2[p] = pk(c2a, c2b);  S2[p] = pk(s2a, s2b);
        C3[p] = pk(c3a, c3b);  S3[p] = pk(s3a, s3b);
    }

    float resA[2][4], resB[2][4];
#pragma unroll
    for (int w = 0; w < 4; w++) {
        ull acc[3][2];
#pragma unroll
        for (int a = 0; a < 3; a++) {
#pragma unroll
            for (int b = 0; b < 3; b++) {
                const int m = a * 3 + b;
                const ulonglong2* g2 = reinterpret_cast<const ulonglong2*>(&sG[w][m][0]);
                ulonglong2 gA = g2[0];   // g0,g1
                ulonglong2 gB = g2[1];   // g2,g3
                ulonglong2 gC = g2[2];   // g4,g5
                ulonglong2 gD = g2[3];   // g6,g7
                ull g8 = sG[w][m][8];
#pragma unroll
                for (int p = 0; p < 2; p++) {
                    // three independent 2-deep chains
                    ull t0 = ffma2(C3[p], gA.y, gA.x);
                    t0 = ffma2(S3[p], gB.x, t0);
                    ull t1 = ffma2(C3[p], gC.x, gB.y);
                    t1 = ffma2(S3[p], gC.y, t1);
                    ull t2 = ffma2(C3[p], gD.y, gD.x);
                    t2 = ffma2(S3[p], g8, t2);
                    ull r = ffma2(C2[p], t1, t0);
                    r = ffma2(S2[p], t2, r);
                    if (b == 0)      acc[a][p] = r;
                    else if (b == 1) acc[a][p] = ffma2(C1[p], r, acc[a][p]);
                    else             acc[a][p] = ffma2(S1[p], r, acc[a][p]);
                }
            }
        }
#pragma unroll
        for (int p = 0; p < 2; p++) {
            ull o = ffma2(C0[p], acc[1][p], acc[0][p]);
            o = ffma2(S0[p], acc[2][p], o);
            upk(o, resA[p][w], resB[p][w]);
        }
    }

#pragma unroll
    for (int p = 0; p < 2; p++) {
        xout[idxs[p]]         = make_float4(resA[p][0], resA[p][1], resA[p][2], resA[p][3]);
        xout[idxs[p] + halfB] = make_float4(resB[p][0], resB[p][1], resB[p][2], resB[p][3]);
    }
}

extern "C" void kernel_launch(void* const* d_in, const int* in_sizes, int n_in,
                              void* d_out, int out_size) {
    // Identify tensors by size: q_weights is tiny (nlayers*4*3), inputs is B*4.
    int xi = 0, wi = 1;
    if (n_in >= 2 && in_sizes[0] < in_sizes[1]) { xi = 1; wi = 0; }
    const float* x  = (const float*)d_in[xi];
    const float* qw = (const float*)d_in[wi];
    int B = in_sizes[xi] / 4;
    int nlayers = in_sizes[wi] / 12;
    int halfB = B / 2;

    setup_kernel<<<1, TPB>>>(qw, nlayers);

    int blocks = (halfB + TPB * 2 - 1) / (TPB * 2);
    qmain_kernel<<<blocks, TPB>>>((const float4*)x, (float4*)d_out, halfB);
}